// round 9
// baseline (speedup 1.0000x reference)
#include <cuda_runtime.h>
#include <cuda_bf16.h>
#include <cstdint>
#include <math.h>

// ---------------------------------------------------------------------------
// Problem constants
// ---------------------------------------------------------------------------
#define NB    8          // batch
#define NW    1000       // windows per batch element
#define WS_   25         // window size
#define D0    256        // latent dim
#define H_    128        // hidden channels
#define NWIN  8000       // total windows
#define PADW  32         // padded rows per window (25 data + 7 zero)
#define ROWS_PAD (NWIN*PADW)   // 256000 padded rows

// ---------------------------------------------------------------------------
// Device scratch (static __device__ arrays -- no allocation)
// ---------------------------------------------------------------------------
__device__ __nv_bfloat16 g_w0p[7 * 256 * 128];   // [tap][ci][co]
__device__ __nv_bfloat16 g_w1p[5 * 128 * 128];
__device__ __nv_bfloat16 g_w2p[5 * 128 * 128];
__device__ __nv_bfloat16 g_act0[(size_t)ROWS_PAD * H_];  // padded (win,32,128)
__device__ float         g_wscore[NWIN];

// ---------------------------------------------------------------------------
// Helpers
// ---------------------------------------------------------------------------
__device__ __forceinline__ float gelu_f(float x) {
    return 0.5f * x * (1.0f + erff(x * 0.70710678118654752f));
}

__device__ __forceinline__ uint32_t smem_u32(const void* p) {
    uint32_t a;
    asm("{ .reg .u64 t; cvta.to.shared.u64 t, %1; cvt.u32.u64 %0, t; }"
        : "=r"(a) : "l"(p));
    return a;
}

__device__ __forceinline__ void cp16(uint32_t dst, const void* src) {
    asm volatile("cp.async.cg.shared.global [%0], [%1], 16;"
                 :: "r"(dst), "l"(src));
}
__device__ __forceinline__ void cp16z(uint32_t dst, const void* src, int sz) {
    asm volatile("cp.async.cg.shared.global [%0], [%1], 16, %2;"
                 :: "r"(dst), "l"(src), "r"(sz));
}
__device__ __forceinline__ void cp_commit() {
    asm volatile("cp.async.commit_group;" ::: "memory");
}
__device__ __forceinline__ void cp_wait0() {
    asm volatile("cp.async.wait_group 0;" ::: "memory");
}

// Fragment load: 2 x ldmatrix.x4 (A) + 4 x ldmatrix.x4.trans (B)
template<int ROWB>
__device__ __forceinline__ void load_frags(
        uint32_t (&a)[2][4], uint32_t (&b)[8][2],
        uint32_t sAu, uint32_t sBcur, int rbase, int koff, int ks,
        int lane, int warp_n) {
    #pragma unroll
    for (int tm = 0; tm < 2; ++tm) {
        int row = rbase + tm * 16 + (lane & 15);
        int kch = koff + ks * 2 + (lane >> 4);
        uint32_t addr = sAu + row * ROWB + (((kch ^ (row & 7))) << 4);
        asm volatile(
            "ldmatrix.sync.aligned.m8n8.x4.shared.b16 {%0,%1,%2,%3}, [%4];"
            : "=r"(a[tm][0]), "=r"(a[tm][1]), "=r"(a[tm][2]), "=r"(a[tm][3])
            : "r"(addr));
    }
    #pragma unroll
    for (int nb = 0; nb < 4; ++nb) {
        int krow = ks * 16 + (lane & 15);
        int nch  = warp_n * 8 + nb * 2 + (lane >> 4);
        uint32_t addr = sBcur + krow * 256 + (((nch ^ (krow & 7))) << 4);
        asm volatile(
            "ldmatrix.sync.aligned.m8n8.x4.trans.shared.b16 {%0,%1,%2,%3}, [%4];"
            : "=r"(b[2 * nb][0]), "=r"(b[2 * nb][1]),
              "=r"(b[2 * nb + 1][0]), "=r"(b[2 * nb + 1][1])
            : "r"(addr));
    }
}

__device__ __forceinline__ void mma16(
        float (&acc)[2][8][4], const uint32_t (&a)[2][4],
        const uint32_t (&b)[8][2]) {
    #pragma unroll
    for (int tm = 0; tm < 2; ++tm)
        #pragma unroll
        for (int tn = 0; tn < 8; ++tn)
            asm volatile(
                "mma.sync.aligned.m16n8k16.row.col.f32.bf16.bf16.f32 "
                "{%0,%1,%2,%3}, {%4,%5,%6,%7}, {%8,%9}, {%0,%1,%2,%3};"
                : "+f"(acc[tm][tn][0]), "+f"(acc[tm][tn][1]),
                  "+f"(acc[tm][tn][2]), "+f"(acc[tm][tn][3])
                : "r"(a[tm][0]), "r"(a[tm][1]), "r"(a[tm][2]), "r"(a[tm][3]),
                  "r"(b[tn][0]), "r"(b[tn][1]));
}

// ---------------------------------------------------------------------------
// Weight prep: transpose conv weights to [tap][ci][co] bf16
// ---------------------------------------------------------------------------
__global__ void prep_weights(const float* __restrict__ w0,
                             const float* __restrict__ w1,
                             const float* __restrict__ w2) {
    int idx = blockIdx.x * blockDim.x + threadIdx.x;
    if (idx < 7 * 256 * 128) {
        int co = idx & 127, ci = (idx >> 7) & 255, tap = idx >> 15;
        g_w0p[idx] = __float2bfloat16(w0[(co * 256 + ci) * 7 + tap]);
    }
    idx -= 7 * 256 * 128;
    if (idx >= 0 && idx < 5 * 128 * 128) {
        int co = idx & 127, ci = (idx >> 7) & 127, tap = idx >> 14;
        g_w1p[idx] = __float2bfloat16(w1[(co * 128 + ci) * 5 + tap]);
        g_w2p[idx] = __float2bfloat16(w2[(co * 128 + ci) * 5 + tap]);
    }
}

// ---------------------------------------------------------------------------
// conv0: one CTA = 128 padded rows x 128 co, 8 warps (M32xN64 warp tiles),
// 64-ci double-buffered cp.async weight stages (28 stages of tap x 256ci).
// (R7 config: best per-FLOP kernel so far.)
// ---------------------------------------------------------------------------
__global__ void __launch_bounds__(256, 2)
conv0_kernel(const float* __restrict__ latents, const float* __restrict__ bias) {
    constexpr int ROWS_A = 144, ROWB = 512, NCH = 32;
    constexpr int SROWS = 64, NSTG = 28, BBUF = SROWS * 256;

    extern __shared__ char smem[];
    char* sA_base = smem;                       // 144*512 swizzled
    char* sB_base = smem + ROWS_A * ROWB;       // 2 x 16KB

    const int tid = threadIdx.x, cta = blockIdx.x;
    const int lane = tid & 31, wid = tid >> 5;
    const int warp_m = wid & 3, warp_n = wid >> 2;
    const long Vbase = (long)cta * 128 - 8;
    const uint32_t sAu = smem_u32(sA_base), sBu = smem_u32(sB_base);

    // B stage-0 prefetch
    #pragma unroll
    for (int idx = tid; idx < SROWS * 16; idx += 256) {
        int ci = idx >> 4, cc = idx & 15;
        cp16(sBu + ci * 256 + ((cc ^ (ci & 7)) << 4),
             g_w0p + (size_t)ci * 128 + cc * 8);
    }
    cp_commit();

    // A staging (latents fp32 -> bf16 swizzled)
    for (int idx = tid; idx < ROWS_A * NCH; idx += 256) {
        int i = idx / NCH, c = idx - i * NCH;
        long V = Vbase + i;
        uint4 pk = make_uint4(0u, 0u, 0u, 0u);
        if (V >= 0 && V < (long)ROWS_PAD) {
            int dr = (int)(V & 31);
            if (dr < WS_) {
                int win = (int)(V >> 5);
                int b = win / NW, wi = win - b * NW;
                const float* src =
                    latents + ((size_t)(b * 25000 + wi * WS_ + dr)) * D0 + c * 8;
                float4 f0 = *(const float4*)src;
                float4 f1 = *((const float4*)src + 1);
                __nv_bfloat162 h0 = __floats2bfloat162_rn(f0.x, f0.y);
                __nv_bfloat162 h1 = __floats2bfloat162_rn(f0.z, f0.w);
                __nv_bfloat162 h2 = __floats2bfloat162_rn(f1.x, f1.y);
                __nv_bfloat162 h3 = __floats2bfloat162_rn(f1.z, f1.w);
                pk.x = *(uint32_t*)&h0; pk.y = *(uint32_t*)&h1;
                pk.z = *(uint32_t*)&h2; pk.w = *(uint32_t*)&h3;
            }
        }
        *(uint4*)(sA_base + i * ROWB + ((c ^ (i & 7)) << 4)) = pk;
    }

    float acc[2][8][4];
    #pragma unroll
    for (int tm = 0; tm < 2; ++tm)
        #pragma unroll
        for (int tn = 0; tn < 8; ++tn)
            #pragma unroll
            for (int j = 0; j < 4; ++j) acc[tm][tn][j] = 0.0f;

    uint32_t fa[2][2][4], fb[2][8][2];
    int buf = 0;
    for (int s = 0; s < NSTG; ++s) {
        cp_wait0();
        __syncthreads();
        if (s + 1 < NSTG) {
            const __nv_bfloat16* src = g_w0p + (size_t)(s + 1) * SROWS * 128;
            uint32_t base = sBu + (buf ^ 1) * BBUF;
            #pragma unroll
            for (int idx = tid; idx < SROWS * 16; idx += 256) {
                int ci = idx >> 4, cc = idx & 15;
                cp16(base + ci * 256 + ((cc ^ (ci & 7)) << 4),
                     src + (size_t)ci * 128 + cc * 8);
            }
            cp_commit();
        }
        const int tap = s >> 2, sub = s & 3;
        const int koff = sub * 8;
        const int rbase = 8 + tap - 3 + warp_m * 32;
        const uint32_t sBcur = sBu + buf * BBUF;

        load_frags<ROWB>(fa[0], fb[0], sAu, sBcur, rbase, koff, 0, lane, warp_n);
        #pragma unroll
        for (int ks = 0; ks < 4; ++ks) {
            if (ks < 3)
                load_frags<ROWB>(fa[(ks+1)&1], fb[(ks+1)&1], sAu, sBcur,
                                 rbase, koff, ks + 1, lane, warp_n);
            mma16(acc, fa[ks & 1], fb[ks & 1]);
        }
        buf ^= 1;
    }

    // Epilogue -> g_act0 (bias + gelu, zero pad rows)
    #pragma unroll
    for (int tm = 0; tm < 2; ++tm) {
        #pragma unroll
        for (int tn = 0; tn < 8; ++tn) {
            int col = warp_n * 64 + tn * 8 + (lane & 3) * 2;
            float b0 = bias[col], b1v = bias[col + 1];
            #pragma unroll
            for (int jh = 0; jh < 2; ++jh) {
                int row = warp_m * 32 + tm * 16 + (lane >> 2) + jh * 8;
                int dr = row & 31;
                float v0 = 0.0f, v1 = 0.0f;
                if (dr < WS_) {
                    v0 = gelu_f(acc[tm][tn][jh * 2 + 0] + b0);
                    v1 = gelu_f(acc[tm][tn][jh * 2 + 1] + b1v);
                }
                size_t R = (size_t)cta * 128 + row;
                __nv_bfloat162 h = __floats2bfloat162_rn(v0, v1);
                *(__nv_bfloat162*)(g_act0 + R * H_ + col) = h;
            }
        }
    }
}

// ---------------------------------------------------------------------------
// Fused conv1+conv2+head. One CTA = 128 rows x 128 co, 8 warps (M32xN64).
// conv1 output stays in smem (sA2); window padding guarantees conv2 taps
// never need data outside this tile. 20 unified cp.async weight stages.
// ---------------------------------------------------------------------------
__global__ void __launch_bounds__(256, 2)
conv12_kernel(const float* __restrict__ bias1, const float* __restrict__ bias2,
              const float* __restrict__ hw1, const float* __restrict__ hb1,
              const float* __restrict__ hw2, const float* __restrict__ hb2) {
    constexpr int ROWS_A = 144, ROWB = 256;
    constexpr int SROWS = 64, BBUF = SROWS * 256;   // 16KB per B stage
    constexpr int OF_A1 = 0;
    constexpr int OF_A2 = 144 * 256;                // 36864
    constexpr int OF_B  = OF_A2 + 144 * 256;        // 73728
    constexpr int OF_FEAT = OF_B + 2 * BBUF;        // 106496

    extern __shared__ char smem[];
    char* sA1_base = smem + OF_A1;
    char* sA2_base = smem + OF_A2;
    float* sFeat   = (float*)(smem + OF_FEAT);

    const int tid = threadIdx.x, cta = blockIdx.x;
    const int lane = tid & 31, wid = tid >> 5;
    const int warp_m = wid & 3, warp_n = wid >> 2;
    const long Vbase = (long)cta * 128 - 8;
    const uint32_t sA1u = smem_u32(sA1_base);
    const uint32_t sA2u = smem_u32(sA2_base);
    const uint32_t sBu  = smem_u32(smem + OF_B);

    // B stage-0 prefetch (conv1 tap0, first 64 ci)
    #pragma unroll
    for (int idx = tid; idx < SROWS * 16; idx += 256) {
        int ci = idx >> 4, cc = idx & 15;
        cp16(sBu + ci * 256 + ((cc ^ (ci & 7)) << 4),
             g_w1p + (size_t)ci * 128 + cc * 8);
    }
    cp_commit();

    // A1 staging from g_act0 (zero-fill out-of-range rows)
    #pragma unroll
    for (int idx = tid; idx < ROWS_A * 16; idx += 256) {
        int i = idx >> 4, c = idx & 15;
        long V = Vbase + i;
        long Vc = V < 0 ? 0 : (V >= (long)ROWS_PAD ? (long)ROWS_PAD - 1 : V);
        int sz = (V >= 0 && V < (long)ROWS_PAD) ? 16 : 0;
        cp16z(sA1u + i * ROWB + ((c ^ (i & 7)) << 4),
              g_act0 + (size_t)Vc * H_ + c * 8, sz);
    }
    cp_commit();

    // Zero sA2 border rows (lead 0..7, trail 136..143); epilogue fills 8..135.
    {
        int row = (tid < 128) ? (tid >> 4) : 136 + ((tid - 128) >> 4);
        int c = tid & 15;
        *(uint4*)(sA2_base + row * ROWB + ((c ^ (row & 7)) << 4)) =
            make_uint4(0u, 0u, 0u, 0u);
    }

    float acc[2][8][4];
    #pragma unroll
    for (int tm = 0; tm < 2; ++tm)
        #pragma unroll
        for (int tn = 0; tn < 8; ++tn)
            #pragma unroll
            for (int j = 0; j < 4; ++j) acc[tm][tn][j] = 0.0f;

    uint32_t fa[2][2][4], fb[2][8][2];
    int buf = 0;

    // 20 stages: 0-9 conv1 (tap x 2 sub-64ci), 10-19 conv2.
    for (int s = 0; s < 20; ++s) {
        cp_wait0();
        __syncthreads();   // B stage s resident (+A1 on s=0, +sA2 epi on s=10)

        if (s + 1 < 20) {  // prefetch next stage's weights
            const __nv_bfloat16* src = (s + 1 < 10)
                ? g_w1p + (size_t)(s + 1) * SROWS * 128
                : g_w2p + (size_t)(s + 1 - 10) * SROWS * 128;
            uint32_t base = sBu + (buf ^ 1) * BBUF;
            #pragma unroll
            for (int idx = tid; idx < SROWS * 16; idx += 256) {
                int ci = idx >> 4, cc = idx & 15;
                cp16(base + ci * 256 + ((cc ^ (ci & 7)) << 4),
                     src + (size_t)ci * 128 + cc * 8);
            }
            cp_commit();
        }

        const int ls   = (s < 10) ? s : s - 10;
        const int tap  = ls >> 1, sub = ls & 1;
        const int koff = sub * 8;
        const int rbase = 8 + tap - 2 + warp_m * 32;
        const uint32_t sAcur = (s < 10) ? sA1u : sA2u;
        const uint32_t sBcur = sBu + buf * BBUF;

        load_frags<ROWB>(fa[0], fb[0], sAcur, sBcur, rbase, koff, 0, lane, warp_n);
        #pragma unroll
        for (int ks = 0; ks < 4; ++ks) {
            if (ks < 3)
                load_frags<ROWB>(fa[(ks+1)&1], fb[(ks+1)&1], sAcur, sBcur,
                                 rbase, koff, ks + 1, lane, warp_n);
            mma16(acc, fa[ks & 1], fb[ks & 1]);
        }

        if (s == 9) {
            // conv1 epilogue -> sA2 (smem), then reset acc for conv2.
            // Next iteration's __syncthreads orders these writes before reads.
            #pragma unroll
            for (int tm = 0; tm < 2; ++tm) {
                #pragma unroll
                for (int tn = 0; tn < 8; ++tn) {
                    int col = warp_n * 64 + tn * 8 + (lane & 3) * 2;
                    float b0 = bias1[col], b1v = bias1[col + 1];
                    #pragma unroll
                    for (int jh = 0; jh < 2; ++jh) {
                        int row = warp_m * 32 + tm * 16 + (lane >> 2) + jh * 8;
                        int dr = row & 31;
                        float v0 = 0.0f, v1 = 0.0f;
                        if (dr < WS_) {
                            v0 = gelu_f(acc[tm][tn][jh * 2 + 0] + b0);
                            v1 = gelu_f(acc[tm][tn][jh * 2 + 1] + b1v);
                        }
                        int i = row + 8;
                        int c = col >> 3;
                        uint32_t off = i * ROWB + ((c ^ (i & 7)) << 4) + (lane & 3) * 4;
                        __nv_bfloat162 h = __floats2bfloat162_rn(v0, v1);
                        *(__nv_bfloat162*)(sA2_base + off) = h;
                        acc[tm][tn][jh * 2 + 0] = 0.0f;
                        acc[tm][tn][jh * 2 + 1] = 0.0f;
                    }
                }
            }
        }
        buf ^= 1;
    }

    // ---- Head: pool over 25 valid rows per window + MLP -------------------
    #pragma unroll
    for (int tn = 0; tn < 8; ++tn) {
        #pragma unroll
        for (int jl = 0; jl < 2; ++jl) {
            int col = warp_n * 64 + tn * 8 + (lane & 3) * 2 + jl;
            float bc = bias2[col];
            float s = 0.0f;
            #pragma unroll
            for (int tm = 0; tm < 2; ++tm)
                #pragma unroll
                for (int jh = 0; jh < 2; ++jh) {
                    int row = warp_m * 32 + tm * 16 + (lane >> 2) + jh * 8;
                    if ((row & 31) < WS_)
                        s += gelu_f(acc[tm][tn][jh * 2 + jl] + bc);
                }
            s += __shfl_xor_sync(0xffffffffu, s, 4);
            s += __shfl_xor_sync(0xffffffffu, s, 8);
            s += __shfl_xor_sync(0xffffffffu, s, 16);
            if ((lane >> 2) == 0)
                sFeat[warp_m * 128 + col] = s * (1.0f / WS_);
        }
    }
    __syncthreads();
    if (wid < 4) {  // one warp per window: MLP head
        int win = wid;
        const float* f = sFeat + win * 128;
        float z = 0.0f;
        #pragma unroll
        for (int q = 0; q < 4; ++q) {
            int j = q * 32 + lane;
            float a = hb1[j];
            const float* wrow = hw1 + (size_t)j * 128;
            #pragma unroll 4
            for (int i = 0; i < 128; i += 4) {
                float4 w = *(const float4*)(wrow + i);
                a += f[i] * w.x + f[i+1] * w.y + f[i+2] * w.z + f[i+3] * w.w;
            }
            z += gelu_f(a) * hw2[j];
        }
        #pragma unroll
        for (int o = 16; o > 0; o >>= 1)
            z += __shfl_xor_sync(0xffffffffu, z, o);
        if (lane == 0)
            g_wscore[cta * 4 + win] = 5.0f / (1.0f + expf(-(z + hb2[0])));
    }
}

// ---------------------------------------------------------------------------
// Finalize: mean over batch, threshold, write outputs
// ---------------------------------------------------------------------------
__global__ void finalize_kernel(float* __restrict__ out, int out_size) {
    int wi = blockIdx.x * blockDim.x + threadIdx.x;
    if (wi < NW) {
        float s = 0.0f;
        #pragma unroll
        for (int b = 0; b < NB; ++b) s += g_wscore[b * NW + wi];
        s *= (1.0f / NB);
        out[wi] = s;
        if (out_size >= 2 * NW)
            out[NW + wi] = (s < 3.5f) ? 1.0f : 0.0f;
    }
}

// ---------------------------------------------------------------------------
// Launch
// ---------------------------------------------------------------------------
extern "C" void kernel_launch(void* const* d_in, const int* in_sizes, int n_in,
                              void* d_out, int out_size) {
    const float* latents = (const float*)d_in[0];
    const float* c0w = (const float*)d_in[1];
    const float* c0b = (const float*)d_in[2];
    const float* c1w = (const float*)d_in[3];
    const float* c1b = (const float*)d_in[4];
    const float* c2w = (const float*)d_in[5];
    const float* c2b = (const float*)d_in[6];
    const float* hw1 = (const float*)d_in[7];
    const float* hb1 = (const float*)d_in[8];
    const float* hw2 = (const float*)d_in[9];
    const float* hb2 = (const float*)d_in[10];

    prep_weights<<<304, 1024>>>(c0w, c1w, c2w);

    {   // conv0: 144*512 A + 2x16KB B = 106496
        constexpr int SMEM = 144 * 512 + 2 * 64 * 256;
        cudaFuncSetAttribute(conv0_kernel,
                             cudaFuncAttributeMaxDynamicSharedMemorySize, SMEM);
        conv0_kernel<<<2000, 256, SMEM>>>(latents, c0b);
    }
    {   // fused conv1+conv2+head: 2x(144*256) A + 2x16KB B + 2KB feat
        constexpr int SMEM = 2 * 144 * 256 + 2 * 64 * 256 + 2048;  // 108544
        cudaFuncSetAttribute(conv12_kernel,
                             cudaFuncAttributeMaxDynamicSharedMemorySize, SMEM);
        conv12_kernel<<<2000, 256, SMEM>>>(c1b, c2b, hw1, hb1, hw2, hb2);
    }

    finalize_kernel<<<1, 1024>>>((float*)d_out, out_size);
}